// round 2
// baseline (speedup 1.0000x reference)
#include <cuda_runtime.h>
#include <math.h>

// Problem constants (fixed shapes from reference)
constexpr int Bc  = 2;
constexpr int Tc  = 2048;
constexpr int Dc  = 1024;
constexpr int Hc  = 16;
constexpr int DKc = 64;     // Dc / Hc
constexpr int Mtot = Bc * Tc;   // 4096 rows for all GEMMs
#define NEG_ (-1.0e9f)

// Scratch (allocation-free rule: __device__ globals)
__device__ float g_Q[Bc * Hc * Tc * DKc];   // [B,H,T,DK]
__device__ float g_K[Bc * Hc * Tc * DKc];
__device__ float g_V[Bc * Hc * Tc * DKc];
__device__ float g_att[Mtot * Dc];          // [B*T, D] attention output (pre out-proj)

// ---------------------------------------------------------------------------
// SGEMM: C[M=4096, N=1024] = A[4096,1024] @ W[1024,1024] + bias
// 128x128 tile, BK=8, 256 threads, 8x8 register micro-tile.
// 2-stage software pipeline: global->reg prefetch overlapped with compute,
// one __syncthreads() per K-slab.
// MODE 0: store into [B,H,T,DK] projection layout.  MODE 1: plain row-major.
// ---------------------------------------------------------------------------
template <int MODE>
__global__ void __launch_bounds__(256) gemm128(const float* __restrict__ A,
                                               const float* __restrict__ W,
                                               const float* __restrict__ bias,
                                               float* __restrict__ C) {
    __shared__ float As[2][8][128];   // transposed A tile: As[buf][k][m]
    __shared__ float Bs[2][8][128];   // Bs[buf][k][n]

    const int tid  = threadIdx.x;
    const int m0   = blockIdx.y << 7;
    const int n0   = blockIdx.x << 7;
    const int arow = tid >> 1;            // 0..127
    const int acol = (tid & 1) << 2;      // 0 or 4
    const int brow = tid >> 5;            // 0..7
    const int bcol = (tid & 31) << 2;     // 0..124
    const int ty   = tid >> 4;            // 0..15
    const int tx   = tid & 15;            // 0..15

    const float* Ap = A + (m0 + arow) * Dc + acol;
    const float* Wp = W + brow * Dc + n0 + bcol;

    float acc[8][8];
#pragma unroll
    for (int i = 0; i < 8; i++)
#pragma unroll
        for (int j = 0; j < 8; j++) acc[i][j] = 0.f;

    // --- prologue: load slab 0 into buffer 0 ---
    {
        const float4 av = *reinterpret_cast<const float4*>(Ap);
        const float4 wv = *reinterpret_cast<const float4*>(Wp);
        As[0][acol + 0][arow] = av.x;
        As[0][acol + 1][arow] = av.y;
        As[0][acol + 2][arow] = av.z;
        As[0][acol + 3][arow] = av.w;
        *reinterpret_cast<float4*>(&Bs[0][brow][bcol]) = wv;
    }
    __syncthreads();

    for (int k0 = 0; k0 < Dc; k0 += 8) {
        const int buf = (k0 >> 3) & 1;
        const bool more = (k0 + 8) < Dc;

        // prefetch next slab into registers (latency hidden behind compute)
        float4 av, wv;
        if (more) {
            av = *reinterpret_cast<const float4*>(Ap + (k0 + 8));
            wv = *reinterpret_cast<const float4*>(Wp + (size_t)(k0 + 8) * Dc);
        }

        // compute current slab
#pragma unroll
        for (int kk = 0; kk < 8; kk++) {
            float a[8], b[8];
            *reinterpret_cast<float4*>(&a[0]) = *reinterpret_cast<const float4*>(&As[buf][kk][ty << 3]);
            *reinterpret_cast<float4*>(&a[4]) = *reinterpret_cast<const float4*>(&As[buf][kk][(ty << 3) + 4]);
            *reinterpret_cast<float4*>(&b[0]) = *reinterpret_cast<const float4*>(&Bs[buf][kk][tx << 3]);
            *reinterpret_cast<float4*>(&b[4]) = *reinterpret_cast<const float4*>(&Bs[buf][kk][(tx << 3) + 4]);
#pragma unroll
            for (int i = 0; i < 8; i++)
#pragma unroll
                for (int j = 0; j < 8; j++)
                    acc[i][j] = fmaf(a[i], b[j], acc[i][j]);
        }

        // stage next slab into the other buffer
        if (more) {
            const int nb = buf ^ 1;
            As[nb][acol + 0][arow] = av.x;
            As[nb][acol + 1][arow] = av.y;
            As[nb][acol + 2][arow] = av.z;
            As[nb][acol + 3][arow] = av.w;
            *reinterpret_cast<float4*>(&Bs[nb][brow][bcol]) = wv;
            __syncthreads();
        }
    }

    float bb[8];
#pragma unroll
    for (int j = 0; j < 8; j++) bb[j] = bias[n0 + (tx << 3) + j];

#pragma unroll
    for (int i = 0; i < 8; i++) {
        const int m = m0 + (ty << 3) + i;
#pragma unroll
        for (int j = 0; j < 8; j++) {
            const int n = n0 + (tx << 3) + j;
            const float v = acc[i][j] + bb[j];
            if (MODE == 0) {
                // [B,T,D] row m -> (b,t); col n -> (h,dk); store [B,H,T,DK]
                const int b  = m >> 11;          // Tc = 2048
                const int t  = m & (Tc - 1);
                const int h  = n >> 6;           // DKc = 64
                const int dk = n & 63;
                C[(((b << 4) + h) * Tc + t) * DKc + dk] = v;
            } else {
                C[(size_t)m * Dc + n] = v;
            }
        }
    }
}

// ---------------------------------------------------------------------------
// Banded attention: one CTA = (b, h, 64-query tile). Keys span [q0-64, q0+127]
// (192 rows). K/V/Q/S resident in shared. Fused bias + mask + softmax.
// ---------------------------------------------------------------------------
// smem layout (floats):
//   Qs:   64*65          = 4160
//   Ks:   192*65         = 12480
//   Vs:   192*65         = 12480
//   Ss:   64*193         = 12352
//   bias: 132
//   rinv: 64
// total = 41668 floats = 166672 bytes
constexpr int ATTN_SMEM_BYTES = 41668 * 4;

__global__ void __launch_bounds__(256) attn_kernel(const float* __restrict__ rel) {
    extern __shared__ float sm[];
    float* Qs      = sm;                      // [64][65]
    float* Ks      = Qs + 64 * 65;            // [192][65]
    float* Vs      = Ks + 192 * 65;           // [192][65]
    float* Ss      = Vs + 192 * 65;           // [64][193]
    float* bias_sh = Ss + 64 * 193;           // [132]
    float* rinv    = bias_sh + 132;           // [64]

    const int tid = threadIdx.x;
    const int qt  = blockIdx.x;   // 0..31
    const int h   = blockIdx.y;   // 0..15
    const int b   = blockIdx.z;   // 0..1
    const int q0  = qt << 6;
    const int k0  = q0 - 64;

    const float* Qg = g_Q + ((b * Hc + h) * Tc + q0) * DKc;
    const float* Kg = g_K + ((b * Hc + h) * Tc) * DKc;
    const float* Vg = g_V + ((b * Hc + h) * Tc) * DKc;

    // ---- load Q tile (64 x 64) ----
    for (int f = tid; f < 64 * 16; f += 256) {
        const int r = f >> 4, c = (f & 15) << 2;
        const float4 v = *reinterpret_cast<const float4*>(Qg + r * DKc + c);
        float* d = Qs + r * 65 + c;
        d[0] = v.x; d[1] = v.y; d[2] = v.z; d[3] = v.w;
    }
    // ---- load K/V band (192 x 64), zero-fill out of range ----
    for (int f = tid; f < 192 * 16; f += 256) {
        const int r = f >> 4, c = (f & 15) << 2;
        const int kg = k0 + r;
        const bool ok = (kg >= 0 && kg < Tc);
        float4 kv = make_float4(0.f, 0.f, 0.f, 0.f);
        float4 vv = make_float4(0.f, 0.f, 0.f, 0.f);
        if (ok) {
            kv = *reinterpret_cast<const float4*>(Kg + kg * DKc + c);
            vv = *reinterpret_cast<const float4*>(Vg + kg * DKc + c);
        }
        float* dk_ = Ks + r * 65 + c;
        dk_[0] = kv.x; dk_[1] = kv.y; dk_[2] = kv.z; dk_[3] = kv.w;
        float* dv_ = Vs + r * 65 + c;
        dv_[0] = vv.x; dv_[1] = vv.y; dv_[2] = vv.z; dv_[3] = vv.w;
    }
    // ---- relative-position bias column for this head: rel dist in [-64,64] ----
    for (int i = tid; i < 129; i += 256)
        bias_sh[i] = rel[(i + 64) * Hc + h];   // table index = rel + MAXD = (i-64)+128
    __syncthreads();

    // ---- S = (Q K^T) * 1/8 + bias, masked ----
    {
        const int ty = tid >> 4, tx = tid & 15;   // 4 q-rows x 12 keys per thread
        float acc[4][12];
#pragma unroll
        for (int i = 0; i < 4; i++)
#pragma unroll
            for (int j = 0; j < 12; j++) acc[i][j] = 0.f;

        for (int d = 0; d < 64; ++d) {
            float qv[4], kv[12];
#pragma unroll
            for (int i = 0; i < 4; i++) qv[i] = Qs[(ty * 4 + i) * 65 + d];
#pragma unroll
            for (int j = 0; j < 12; j++) kv[j] = Ks[(tx * 12 + j) * 65 + d];
#pragma unroll
            for (int i = 0; i < 4; i++)
#pragma unroll
                for (int j = 0; j < 12; j++)
                    acc[i][j] = fmaf(qv[i], kv[j], acc[i][j]);
        }
#pragma unroll
        for (int i = 0; i < 4; i++) {
            const int q = ty * 4 + i;
#pragma unroll
            for (int j = 0; j < 12; j++) {
                const int kk = tx * 12 + j;
                const int kg = k0 + kk;
                const int rd = kk - 64 - q;           // = kg - (q0+q), in [-127..127]
                float s;
                if (kg >= 0 && kg < Tc && rd >= -64 && rd <= 64)
                    s = acc[i][j] * 0.125f + bias_sh[rd + 64];
                else
                    s = NEG_;
                Ss[q * 193 + kk] = s;
            }
        }
    }
    __syncthreads();

    // ---- softmax per row (4 lanes per row); store unnormalized exp + 1/sum ----
    {
        const int row = tid >> 2, sub = tid & 3;
        float m = -1e30f;
        for (int kk = sub; kk < 192; kk += 4) m = fmaxf(m, Ss[row * 193 + kk]);
        m = fmaxf(m, __shfl_xor_sync(0xffffffffu, m, 1));
        m = fmaxf(m, __shfl_xor_sync(0xffffffffu, m, 2));
        float l = 0.f;
        for (int kk = sub; kk < 192; kk += 4) {
            const float e = __expf(Ss[row * 193 + kk] - m);
            Ss[row * 193 + kk] = e;
            l += e;
        }
        l += __shfl_xor_sync(0xffffffffu, l, 1);
        l += __shfl_xor_sync(0xffffffffu, l, 2);
        if (sub == 0) rinv[row] = 1.f / l;
    }
    __syncthreads();

    // ---- O = P V  (64x192 @ 192x64), write [B,T,H*DK] ----
    {
        const int ty = tid >> 4, tx = tid & 15;   // 4x4 micro-tile
        float o[4][4];
#pragma unroll
        for (int i = 0; i < 4; i++)
#pragma unroll
            for (int j = 0; j < 4; j++) o[i][j] = 0.f;

        for (int kk = 0; kk < 192; ++kk) {
            float p[4], v[4];
#pragma unroll
            for (int i = 0; i < 4; i++) p[i] = Ss[(ty * 4 + i) * 193 + kk];
#pragma unroll
            for (int j = 0; j < 4; j++) v[j] = Vs[kk * 65 + (tx << 2) + j];
#pragma unroll
            for (int i = 0; i < 4; i++)
#pragma unroll
                for (int j = 0; j < 4; j++)
                    o[i][j] = fmaf(p[i], v[j], o[i][j]);
        }
#pragma unroll
        for (int i = 0; i < 4; i++) {
            const int q = ty * 4 + i;
            const float s = rinv[q];
            float4 ov = make_float4(o[i][0] * s, o[i][1] * s, o[i][2] * s, o[i][3] * s);
            *reinterpret_cast<float4*>(g_att + (size_t)(b * Tc + q0 + q) * Dc + h * DKc + (tx << 2)) = ov;
        }
    }
}

// ---------------------------------------------------------------------------
extern "C" void kernel_launch(void* const* d_in, const int* in_sizes, int n_in,
                              void* d_out, int out_size) {
    const float* q_in = (const float*)d_in[0];
    const float* k_in = (const float*)d_in[1];
    const float* v_in = (const float*)d_in[2];
    const float* Wq   = (const float*)d_in[3];
    const float* bq   = (const float*)d_in[4];
    const float* Wk   = (const float*)d_in[5];
    const float* bk   = (const float*)d_in[6];
    const float* Wv   = (const float*)d_in[7];
    const float* bv   = (const float*)d_in[8];
    const float* Wo   = (const float*)d_in[9];
    const float* bo   = (const float*)d_in[10];
    const float* rel  = (const float*)d_in[11];
    float* out = (float*)d_out;

    float *pQ, *pK, *pV, *pAtt;
    cudaGetSymbolAddress((void**)&pQ, g_Q);
    cudaGetSymbolAddress((void**)&pK, g_K);
    cudaGetSymbolAddress((void**)&pV, g_V);
    cudaGetSymbolAddress((void**)&pAtt, g_att);

    cudaFuncSetAttribute(attn_kernel, cudaFuncAttributeMaxDynamicSharedMemorySize,
                         ATTN_SMEM_BYTES);

    dim3 gg(Dc / 128, Mtot / 128);   // (8, 32)
    gemm128<0><<<gg, 256>>>(q_in, Wq, bq, pQ);
    gemm128<0><<<gg, 256>>>(k_in, Wk, bk, pK);
    gemm128<0><<<gg, 256>>>(v_in, Wv, bv, pV);

    attn_kernel<<<dim3(Tc / 64, Hc, Bc), 256, ATTN_SMEM_BYTES>>>(rel);

    gemm128<1><<<gg, 256>>>(pAtt, Wo, bo, out);
}

// round 4
// speedup vs baseline: 1.6859x; 1.6859x over previous
#include <cuda_runtime.h>
#include <cuda_bf16.h>
#include <math.h>

// Problem constants (fixed shapes from reference)
constexpr int Bc  = 2;
constexpr int Tc  = 2048;
constexpr int Dc  = 1024;
constexpr int Hc  = 16;
constexpr int DKc = 64;         // Dc / Hc
constexpr int Mtot = Bc * Tc;   // 4096 rows for all GEMMs
#define NEG_ (-1.0e9f)

// Scratch (allocation-free rule: __device__ globals)
__device__ float g_Q[Bc * Hc * Tc * DKc];   // [B,H,T,DK]
__device__ float g_K[Bc * Hc * Tc * DKc];
__device__ float g_V[Bc * Hc * Tc * DKc];
__device__ float g_att[Mtot * Dc];          // [B*T, D] attention output (pre out-proj)

// ---------------------------------------------------------------------------
// Tensor-core helpers (warp-level mma.sync path; fragment layouts per PTX ISA)
// ---------------------------------------------------------------------------
__device__ __forceinline__ void ldsm_x4(unsigned (&r)[4], const void* p) {
    unsigned addr = (unsigned)__cvta_generic_to_shared(p);
    asm volatile("ldmatrix.sync.aligned.m8n8.x4.shared.b16 {%0,%1,%2,%3}, [%4];"
                 : "=r"(r[0]), "=r"(r[1]), "=r"(r[2]), "=r"(r[3]) : "r"(addr));
}
__device__ __forceinline__ void ldsm_x2(unsigned (&r)[2], const void* p) {
    unsigned addr = (unsigned)__cvta_generic_to_shared(p);
    asm volatile("ldmatrix.sync.aligned.m8n8.x2.shared.b16 {%0,%1}, [%2];"
                 : "=r"(r[0]), "=r"(r[1]) : "r"(addr));
}
__device__ __forceinline__ void mma16816(float (&d)[4], const unsigned (&a)[4],
                                         const unsigned (&b)[2]) {
    asm volatile(
        "mma.sync.aligned.m16n8k16.row.col.f32.bf16.bf16.f32 "
        "{%0,%1,%2,%3}, {%4,%5,%6,%7}, {%8,%9}, {%0,%1,%2,%3};"
        : "+f"(d[0]), "+f"(d[1]), "+f"(d[2]), "+f"(d[3])
        : "r"(a[0]), "r"(a[1]), "r"(a[2]), "r"(a[3]), "r"(b[0]), "r"(b[1]));
}

// ---------------------------------------------------------------------------
// bf16x3 GEMM: C[4096,1024] = A[4096,1024] @ W[1024,1024] + bias, fp32 in/out.
// A,W split on the fly into (hi,lo) bf16; acc = Ah*Wh + Ah*Wl + Al*Wh (fp32).
// 128x128 CTA tile, BK=16, 256 threads (8 warps x 64x32 warp tile), double-
// buffered smem, global->reg prefetch overlapped with mma.
// MODE 0: store into [B,H,T,DK] projection layout.  MODE 1: plain row-major.
// ---------------------------------------------------------------------------
constexpr int GPAD = 24;                       // row pad (conflict-free ldmatrix)
constexpr int GTILE = 128 * GPAD;              // elements per [128][24] tile
constexpr int GEMM_SMEM_BYTES = 4 * 2 * GTILE * 2;   // 4 arrays x 2 bufs x bf16 = 48KB

template <int MODE>
__global__ void __launch_bounds__(256) gemm_bf16x3(const float* __restrict__ A,
                                                   const float* __restrict__ W,
                                                   const float* __restrict__ bias,
                                                   float* __restrict__ C) {
    extern __shared__ __nv_bfloat16 smg[];
    __nv_bfloat16* Ah = smg;                 // [2][128][24]
    __nv_bfloat16* Al = Ah + 2 * GTILE;
    __nv_bfloat16* Bh = Al + 2 * GTILE;      // stored [n][k]
    __nv_bfloat16* Bl = Bh + 2 * GTILE;

    const int tid  = threadIdx.x;
    const int lane = tid & 31;
    const int warp = tid >> 5;
    const int m0   = blockIdx.y << 7;
    const int n0   = blockIdx.x << 7;
    const int wm   = (warp >> 2) << 6;     // 0 / 64
    const int wn   = (warp & 3)  << 5;     // 0..96

    // global-load mapping
    const int arow = tid >> 1;             // 0..127
    const int ac0  = (tid & 1) << 3;       // 0 / 8
    const int krow = tid >> 4;             // 0..15
    const int nc0  = (tid & 15) << 3;      // 0..120

    const float* Apt = A + (size_t)(m0 + arow) * Dc + ac0;
    const float* Wpt = W + (size_t)krow * Dc + n0 + nc0;

    float acc[4][4][4];
#pragma unroll
    for (int i = 0; i < 4; i++)
#pragma unroll
        for (int j = 0; j < 4; j++)
#pragma unroll
            for (int c = 0; c < 4; c++) acc[i][j][c] = 0.f;

    auto stage = [&](int nb, const float4& a0, const float4& a1,
                     const float4& w0, const float4& w1) {
        float av[8] = {a0.x, a0.y, a0.z, a0.w, a1.x, a1.y, a1.z, a1.w};
        float wv[8] = {w0.x, w0.y, w0.z, w0.w, w1.x, w1.y, w1.z, w1.w};
        // A rows are contiguous in k: pack hi/lo pairs into 32-bit stores.
#pragma unroll
        for (int j = 0; j < 8; j += 2) {
            __nv_bfloat16 h0 = __float2bfloat16(av[j]);
            __nv_bfloat16 h1 = __float2bfloat16(av[j + 1]);
            __nv_bfloat16 l0 = __float2bfloat16(av[j] - __bfloat162float(h0));
            __nv_bfloat16 l1 = __float2bfloat16(av[j + 1] - __bfloat162float(h1));
            *reinterpret_cast<__nv_bfloat162*>(&Ah[nb * GTILE + arow * GPAD + ac0 + j]) =
                __nv_bfloat162(h0, h1);
            *reinterpret_cast<__nv_bfloat162*>(&Al[nb * GTILE + arow * GPAD + ac0 + j]) =
                __nv_bfloat162(l0, l1);
        }
        // W staged transposed [n][k]: scalar stores (non-contiguous).
#pragma unroll
        for (int j = 0; j < 8; j++) {
            __nv_bfloat16 hi = __float2bfloat16(wv[j]);
            __nv_bfloat16 lo = __float2bfloat16(wv[j] - __bfloat162float(hi));
            Bh[nb * GTILE + (nc0 + j) * GPAD + krow] = hi;
            Bl[nb * GTILE + (nc0 + j) * GPAD + krow] = lo;
        }
    };

    // prologue: slab 0 -> buffer 0
    {
        float4 a0 = *reinterpret_cast<const float4*>(Apt);
        float4 a1 = *reinterpret_cast<const float4*>(Apt + 4);
        float4 w0 = *reinterpret_cast<const float4*>(Wpt);
        float4 w1 = *reinterpret_cast<const float4*>(Wpt + 4);
        stage(0, a0, a1, w0, w1);
    }
    __syncthreads();

    const int l15 = lane & 15;
    const int aRowOff = l15;                 // + wm + im*16
    const int aColOff = (lane >> 4) << 3;    // 0 / 8
    const int bRowOff = l15 & 7;             // + wn + in*8
    const int bColOff = ((l15 >> 3) & 1) << 3;

#pragma unroll 1
    for (int ks = 0; ks < Dc / 16; ks++) {
        const int buf = ks & 1;
        const bool more = ks < (Dc / 16 - 1);

        float4 a0, a1, w0, w1;
        if (more) {
            const int k = (ks + 1) << 4;
            a0 = *reinterpret_cast<const float4*>(Apt + k);
            a1 = *reinterpret_cast<const float4*>(Apt + k + 4);
            w0 = *reinterpret_cast<const float4*>(Wpt + (size_t)k * Dc);
            w1 = *reinterpret_cast<const float4*>(Wpt + (size_t)k * Dc + 4);
        }

        unsigned ahi[4][4], alo[4][4];
#pragma unroll
        for (int im = 0; im < 4; im++) {
            const int r = wm + (im << 4) + aRowOff;
            ldsm_x4(ahi[im], &Ah[buf * GTILE + r * GPAD + aColOff]);
            ldsm_x4(alo[im], &Al[buf * GTILE + r * GPAD + aColOff]);
        }
#pragma unroll
        for (int in = 0; in < 4; in++) {
            unsigned bhi[2], blo[2];
            const int r = wn + (in << 3) + bRowOff;
            ldsm_x2(bhi, &Bh[buf * GTILE + r * GPAD + bColOff]);
            ldsm_x2(blo, &Bl[buf * GTILE + r * GPAD + bColOff]);
#pragma unroll
            for (int im = 0; im < 4; im++) {
                mma16816(acc[im][in], ahi[im], bhi);
                mma16816(acc[im][in], ahi[im], blo);
                mma16816(acc[im][in], alo[im], bhi);
            }
        }

        if (more) stage(buf ^ 1, a0, a1, w0, w1);
        __syncthreads();
    }

    // epilogue: bias + store (fragment mapping: c0 (r,c), c1 (r,c+1), c2 (r+8,c), c3 (r+8,c+1))
#pragma unroll
    for (int im = 0; im < 4; im++) {
        const int row = m0 + wm + (im << 4) + (lane >> 2);
#pragma unroll
        for (int in = 0; in < 4; in++) {
            const int col = n0 + wn + (in << 3) + ((lane & 3) << 1);
            const float b0 = bias[col], b1 = bias[col + 1];
            float v00 = acc[im][in][0] + b0;
            float v01 = acc[im][in][1] + b1;
            float v10 = acc[im][in][2] + b0;
            float v11 = acc[im][in][3] + b1;
            if (MODE == 0) {
                // row m -> (b,t); col n -> (h,dk); store [B,H,T,DK]
#pragma unroll
                for (int e = 0; e < 4; e++) {
                    const int m = row + ((e >> 1) << 3);
                    const int n = col + (e & 1);
                    const float v = (e == 0) ? v00 : (e == 1) ? v01 : (e == 2) ? v10 : v11;
                    const int b  = m >> 11;
                    const int t  = m & (Tc - 1);
                    const int h  = n >> 6;
                    const int dk = n & 63;
                    C[(((b << 4) + h) * Tc + t) * DKc + dk] = v;
                }
            } else {
                C[(size_t)row * Dc + col] = v00;
                C[(size_t)row * Dc + col + 1] = v01;
                C[(size_t)(row + 8) * Dc + col] = v10;
                C[(size_t)(row + 8) * Dc + col + 1] = v11;
            }
        }
    }
}

// ---------------------------------------------------------------------------
// Banded attention: one CTA = (b, h, 64-query tile). Keys span [q0-64, q0+127]
// (192 rows). 512 threads for occupancy. Fused bias+mask+softmax.
// ---------------------------------------------------------------------------
constexpr int ATTN_SMEM_BYTES = (64 * 65 + 192 * 65 + 192 * 65 + 64 * 193 + 132 + 64) * 4;

__global__ void __launch_bounds__(512) attn_kernel(const float* __restrict__ rel) {
    extern __shared__ float sm[];
    float* Qs      = sm;                      // [64][65]
    float* Ks      = Qs + 64 * 65;            // [192][65]
    float* Vs      = Ks + 192 * 65;           // [192][65]
    float* Ss      = Vs + 192 * 65;           // [64][193]
    float* bias_sh = Ss + 64 * 193;           // [132]
    float* rinv    = bias_sh + 132;           // [64]

    const int tid = threadIdx.x;
    const int qt  = blockIdx.x;
    const int h   = blockIdx.y;
    const int b   = blockIdx.z;
    const int q0  = qt << 6;
    const int k0  = q0 - 64;

    const float* Qg = g_Q + ((b * Hc + h) * Tc + q0) * DKc;
    const float* Kg = g_K + ((b * Hc + h) * Tc) * DKc;
    const float* Vg = g_V + ((b * Hc + h) * Tc) * DKc;

    // ---- load Q tile (64 x 64) ----
    for (int f = tid; f < 64 * 16; f += 512) {
        const int r = f >> 4, c = (f & 15) << 2;
        const float4 v = *reinterpret_cast<const float4*>(Qg + r * DKc + c);
        float* d = Qs + r * 65 + c;
        d[0] = v.x; d[1] = v.y; d[2] = v.z; d[3] = v.w;
    }
    // ---- load K/V band (192 x 64), zero-fill out of range ----
    for (int f = tid; f < 192 * 16; f += 512) {
        const int r = f >> 4, c = (f & 15) << 2;
        const int kg = k0 + r;
        const bool ok = (kg >= 0 && kg < Tc);
        float4 kv = make_float4(0.f, 0.f, 0.f, 0.f);
        float4 vv = make_float4(0.f, 0.f, 0.f, 0.f);
        if (ok) {
            kv = *reinterpret_cast<const float4*>(Kg + kg * DKc + c);
            vv = *reinterpret_cast<const float4*>(Vg + kg * DKc + c);
        }
        float* dk_ = Ks + r * 65 + c;
        dk_[0] = kv.x; dk_[1] = kv.y; dk_[2] = kv.z; dk_[3] = kv.w;
        float* dv_ = Vs + r * 65 + c;
        dv_[0] = vv.x; dv_[1] = vv.y; dv_[2] = vv.z; dv_[3] = vv.w;
    }
    for (int i = tid; i < 129; i += 512)
        bias_sh[i] = rel[(i + 64) * Hc + h];
    __syncthreads();

    // ---- S = (Q K^T)/8 + bias, masked.  2 q-rows x 12 keys per thread ----
    {
        const int ty = tid >> 4, tx = tid & 15;
        float accm[2][12];
#pragma unroll
        for (int i = 0; i < 2; i++)
#pragma unroll
            for (int j = 0; j < 12; j++) accm[i][j] = 0.f;

        for (int d = 0; d < 64; ++d) {
            float qv[2], kv[12];
#pragma unroll
            for (int i = 0; i < 2; i++) qv[i] = Qs[(ty * 2 + i) * 65 + d];
#pragma unroll
            for (int j = 0; j < 12; j++) kv[j] = Ks[(tx * 12 + j) * 65 + d];
#pragma unroll
            for (int i = 0; i < 2; i++)
#pragma unroll
                for (int j = 0; j < 12; j++)
                    accm[i][j] = fmaf(qv[i], kv[j], accm[i][j]);
        }
#pragma unroll
        for (int i = 0; i < 2; i++) {
            const int q = ty * 2 + i;
#pragma unroll
            for (int j = 0; j < 12; j++) {
                const int kk = tx * 12 + j;
                const int kg = k0 + kk;
                const int rd = kk - 64 - q;
                float s;
                if (kg >= 0 && kg < Tc && rd >= -64 && rd <= 64)
                    s = accm[i][j] * 0.125f + bias_sh[rd + 64];
                else
                    s = NEG_;
                Ss[q * 193 + kk] = s;
            }
        }
    }
    __syncthreads();

    // ---- softmax per row (8 lanes per row) ----
    {
        const int row = tid >> 3, sub = tid & 7;
        float m = -1e30f;
        for (int kk = sub; kk < 192; kk += 8) m = fmaxf(m, Ss[row * 193 + kk]);
        m = fmaxf(m, __shfl_xor_sync(0xffffffffu, m, 1));
        m = fmaxf(m, __shfl_xor_sync(0xffffffffu, m, 2));
        m = fmaxf(m, __shfl_xor_sync(0xffffffffu, m, 4));
        float l = 0.f;
        for (int kk = sub; kk < 192; kk += 8) {
            const float e = __expf(Ss[row * 193 + kk] - m);
            Ss[row * 193 + kk] = e;
            l += e;
        }
        l += __shfl_xor_sync(0xffffffffu, l, 1);
        l += __shfl_xor_sync(0xffffffffu, l, 2);
        l += __shfl_xor_sync(0xffffffffu, l, 4);
        if (sub == 0) rinv[row] = 1.f / l;
    }
    __syncthreads();

    // ---- O = P V  (64x192 @ 192x64): 2 q x 4 d per thread ----
    {
        const int ty = tid >> 4, tx = tid & 15;
        float o[2][4];
#pragma unroll
        for (int i = 0; i < 2; i++)
#pragma unroll
            for (int j = 0; j < 4; j++) o[i][j] = 0.f;

        for (int kk = 0; kk < 192; ++kk) {
            float p[2], v[4];
#pragma unroll
            for (int i = 0; i < 2; i++) p[i] = Ss[(ty * 2 + i) * 193 + kk];
#pragma unroll
            for (int j = 0; j < 4; j++) v[j] = Vs[kk * 65 + (tx << 2) + j];
#pragma unroll
            for (int i = 0; i < 2; i++)
#pragma unroll
                for (int j = 0; j < 4; j++)
                    o[i][j] = fmaf(p[i], v[j], o[i][j]);
        }
#pragma unroll
        for (int i = 0; i < 2; i++) {
            const int q = ty * 2 + i;
            const float s = rinv[q];
            float4 ov = make_float4(o[i][0] * s, o[i][1] * s, o[i][2] * s, o[i][3] * s);
            *reinterpret_cast<float4*>(g_att + (size_t)(b * Tc + q0 + q) * Dc + h * DKc + (tx << 2)) = ov;
        }
    }
}

// ---------------------------------------------------------------------------
extern "C" void kernel_launch(void* const* d_in, const int* in_sizes, int n_in,
                              void* d_out, int out_size) {
    const float* q_in = (const float*)d_in[0];
    const float* k_in = (const float*)d_in[1];
    const float* v_in = (const float*)d_in[2];
    const float* Wq   = (const float*)d_in[3];
    const float* bq   = (const float*)d_in[4];
    const float* Wk   = (const float*)d_in[5];
    const float* bk   = (const float*)d_in[6];
    const float* Wv   = (const float*)d_in[7];
    const float* bv   = (const float*)d_in[8];
    const float* Wo   = (const float*)d_in[9];
    const float* bo   = (const float*)d_in[10];
    const float* rel  = (const float*)d_in[11];
    float* out = (float*)d_out;

    float *pQ, *pK, *pV, *pAtt;
    cudaGetSymbolAddress((void**)&pQ, g_Q);
    cudaGetSymbolAddress((void**)&pK, g_K);
    cudaGetSymbolAddress((void**)&pV, g_V);
    cudaGetSymbolAddress((void**)&pAtt, g_att);

    cudaFuncSetAttribute(attn_kernel, cudaFuncAttributeMaxDynamicSharedMemorySize,
                         ATTN_SMEM_BYTES);
    cudaFuncSetAttribute(gemm_bf16x3<0>, cudaFuncAttributeMaxDynamicSharedMemorySize,
                         GEMM_SMEM_BYTES);
    cudaFuncSetAttribute(gemm_bf16x3<1>, cudaFuncAttributeMaxDynamicSharedMemorySize,
                         GEMM_SMEM_BYTES);

    dim3 gg(Dc / 128, Mtot / 128);   // (8, 32)
    gemm_bf16x3<0><<<gg, 256, GEMM_SMEM_BYTES>>>(q_in, Wq, bq, pQ);
    gemm_bf16x3<0><<<gg, 256, GEMM_SMEM_BYTES>>>(k_in, Wk, bk, pK);
    gemm_bf16x3<0><<<gg, 256, GEMM_SMEM_BYTES>>>(v_in, Wv, bv, pV);

    attn_kernel<<<dim3(Tc / 64, Hc, Bc), 512, ATTN_SMEM_BYTES>>>(rel);

    gemm_bf16x3<1><<<gg, 256, GEMM_SMEM_BYTES>>>(pAtt, Wo, bo, out);
}